// round 1
// baseline (speedup 1.0000x reference)
#include <cuda_runtime.h>
#include <cstddef>

// Problem constants
#define Tn 10
#define Bn 4
#define Cc 64
#define Hh 64
#define Ww 64
#define HWp 4096          // Hh*Ww
#define TILE 16
#define RS 20             // smem row stride (bank-conflict-free split halves)
#define ICS 360           // 18 rows * RS
#define SM_IN (64*ICS)    // 23040 floats
#define SM_W  (32*72)     // 2304 floats (32 oc x 8 ic x 9 taps, rest padded to 72)
#define SMEM_FLOATS (SM_IN + SM_W)

// Recurrent state + inter-kernel scratch (allocation-free: device globals)
__device__ float g_prev_y [Bn*Cc*HWp];
__device__ float g_h      [Bn*Cc*HWp];
__device__ float g_gate_in[Bn*Cc*HWp];   // prev_y * reset_gate
__device__ float g_upd    [Bn*Cc*HWp];   // update gate
__device__ float g_thr    [Bn*HWp];      // sigmoid(thr_logit), 1 channel

__device__ __forceinline__ float sigmoidf_(float x) { return 1.0f / (1.0f + __expf(-x)); }

// Load one 18x18 halo tile for all 64 input channels into smem (zero-padded SAME).
__device__ __forceinline__ void load_tile(const float* __restrict__ in, int b,
                                          int ty0, int tx0, float* s_in, int tid)
{
    for (int idx = tid; idx < 64 * 324; idx += 256) {
        int ic  = idx / 324;
        int rem = idx - ic * 324;
        int r   = rem / 18;
        int cc  = rem - r * 18;
        int gy  = ty0 + r - 1;
        int gx  = tx0 + cc - 1;
        float v = 0.0f;
        if (gy >= 0 && gy < Hh && gx >= 0 && gx < Ww)
            v = in[((b * Cc + ic) * Hh + gy) * Ww + gx];
        s_in[ic * ICS + r * RS + cc] = v;
    }
}

// ---------------------------------------------------------------------------
// Kernel A: rz = conv3x3(prev_y, w_rz) + b_rz (129 channels)
//   grp 0..3: 32 oc each (z: 0..63, r: 64..127) + gate epilogue
//   grp 4   : oc 128 (threshold logit) -> g_thr
// ---------------------------------------------------------------------------
__global__ void __launch_bounds__(256, 2)
kA(const float* __restrict__ xt, const float* __restrict__ w_rz,
   const float* __restrict__ b_rz, int t)
{
    extern __shared__ float smem[];
    float* s_in = smem;
    float* s_w  = smem + SM_IN;

    int tid  = threadIdx.x;
    int tile = blockIdx.x;   // 0..15
    int grp  = blockIdx.y;   // 0..4
    int b    = blockIdx.z;   // 0..3
    int ty0  = (tile >> 2) * TILE;
    int tx0  = (tile & 3) * TILE;

    if (t > 0) load_tile(g_prev_y, b, ty0, tx0, s_in, tid);

    if (grp < 4) {
        int oc_base = grp * 32;
        float acc[8][4];
        #pragma unroll
        for (int k = 0; k < 8; k++)
            #pragma unroll
            for (int i = 0; i < 4; i++) acc[k][i] = 0.0f;

        int pixg = tid & 63;
        int ocq  = tid >> 6;           // 0..3 (constant within a warp)
        int px   = pixg & 15;
        int pyb  = (pixg >> 4) << 2;   // 0,4,8,12

        if (t > 0) {
            for (int cc0 = 0; cc0 < 64; cc0 += 8) {
                __syncthreads();   // s_in ready (1st iter) / previous chunk consumed
                for (int i = tid; i < 2304; i += 256) {
                    int ocl  = i / 72;
                    int rest = i - ocl * 72;  // = icl*9 + tap
                    s_w[i] = w_rz[(oc_base + ocl) * 576 + cc0 * 9 + rest];
                }
                __syncthreads();
                #pragma unroll
                for (int icl = 0; icl < 8; icl++) {
                    const float* sin = s_in + (cc0 + icl) * ICS;
                    const float* sw  = s_w + ocq * 8 * 72 + icl * 9;
                    #pragma unroll
                    for (int dy = 0; dy < 3; dy++) {
                        #pragma unroll
                        for (int dx = 0; dx < 3; dx++) {
                            int tap = dy * 3 + dx;
                            float x0 = sin[(pyb + 0 + dy) * RS + px + dx];
                            float x1 = sin[(pyb + 1 + dy) * RS + px + dx];
                            float x2 = sin[(pyb + 2 + dy) * RS + px + dx];
                            float x3 = sin[(pyb + 3 + dy) * RS + px + dx];
                            #pragma unroll
                            for (int k = 0; k < 8; k++) {
                                float w = sw[k * 72 + tap];
                                acc[k][0] += w * x0;
                                acc[k][1] += w * x1;
                                acc[k][2] += w * x2;
                                acc[k][3] += w * x3;
                            }
                        }
                    }
                }
            }
        }

        // Epilogue: gates
        #pragma unroll
        for (int k = 0; k < 8; k++) {
            int oc = oc_base + ocq * 8 + k;
            float bias = b_rz[oc];
            #pragma unroll
            for (int i = 0; i < 4; i++) {
                int gy  = ty0 + pyb + i;
                int gx  = tx0 + px;
                int pix = gy * Ww + gx;
                float xi = xt[((((size_t)t * Bn + b) * 192) + oc) * HWp + pix];
                float s  = sigmoidf_(acc[k][i] + bias + xi);
                if (oc < 64) {
                    g_upd[(b * Cc + oc) * HWp + pix] = s;   // update gate
                } else {
                    int c = oc - 64;
                    float py = 0.0f;
                    if (t > 0)  // prev_y tile already in smem at channel c
                        py = s_in[c * ICS + (pyb + i + 1) * RS + (px + 1)];
                    g_gate_in[(b * Cc + c) * HWp + pix] = py * s;  // prev_y * reset
                }
            }
        }
    } else {
        // threshold channel (oc = 128): 1 output channel, 1 pixel per thread
        for (int i = tid; i < 576; i += 256)
            s_w[i] = w_rz[128 * 576 + i];
        __syncthreads();
        float acc = 0.0f;
        int px = tid & 15;
        int py = tid >> 4;
        if (t > 0) {
            for (int ic = 0; ic < 64; ic++) {
                const float* sin = s_in + ic * ICS;
                const float* sw  = s_w + ic * 9;
                #pragma unroll
                for (int dy = 0; dy < 3; dy++)
                    #pragma unroll
                    for (int dx = 0; dx < 3; dx++)
                        acc += sw[dy * 3 + dx] * sin[(py + dy) * RS + px + dx];
            }
        }
        int pix = (ty0 + py) * Ww + (tx0 + px);
        g_thr[b * HWp + pix] = sigmoidf_(acc + b_rz[128]);
    }
}

// ---------------------------------------------------------------------------
// Kernel B: f = conv3x3(gate_in, w_f) + b_f + xi_f; full cell update + outputs
// ---------------------------------------------------------------------------
__global__ void __launch_bounds__(256, 2)
kB(const float* __restrict__ xt, const float* __restrict__ w_f,
   const float* __restrict__ b_f, float* __restrict__ out, int t)
{
    extern __shared__ float smem[];
    float* s_in = smem;
    float* s_w  = smem + SM_IN;

    int tid  = threadIdx.x;
    int tile = blockIdx.x;   // 0..15
    int grp  = blockIdx.y;   // 0..1
    int b    = blockIdx.z;
    int ty0  = (tile >> 2) * TILE;
    int tx0  = (tile & 3) * TILE;

    load_tile(g_gate_in, b, ty0, tx0, s_in, tid);  // valid even at t=0 (zeros written by kA)

    int oc_base = grp * 32;
    float acc[8][4];
    #pragma unroll
    for (int k = 0; k < 8; k++)
        #pragma unroll
        for (int i = 0; i < 4; i++) acc[k][i] = 0.0f;

    int pixg = tid & 63;
    int ocq  = tid >> 6;
    int px   = pixg & 15;
    int pyb  = (pixg >> 4) << 2;

    for (int cc0 = 0; cc0 < 64; cc0 += 8) {
        __syncthreads();
        for (int i = tid; i < 2304; i += 256) {
            int ocl  = i / 72;
            int rest = i - ocl * 72;
            s_w[i] = w_f[(oc_base + ocl) * 576 + cc0 * 9 + rest];
        }
        __syncthreads();
        #pragma unroll
        for (int icl = 0; icl < 8; icl++) {
            const float* sin = s_in + (cc0 + icl) * ICS;
            const float* sw  = s_w + ocq * 8 * 72 + icl * 9;
            #pragma unroll
            for (int dy = 0; dy < 3; dy++) {
                #pragma unroll
                for (int dx = 0; dx < 3; dx++) {
                    int tap = dy * 3 + dx;
                    float x0 = sin[(pyb + 0 + dy) * RS + px + dx];
                    float x1 = sin[(pyb + 1 + dy) * RS + px + dx];
                    float x2 = sin[(pyb + 2 + dy) * RS + px + dx];
                    float x3 = sin[(pyb + 3 + dy) * RS + px + dx];
                    #pragma unroll
                    for (int k = 0; k < 8; k++) {
                        float w = sw[k * 72 + tap];
                        acc[k][0] += w * x0;
                        acc[k][1] += w * x1;
                        acc[k][2] += w * x2;
                        acc[k][3] += w * x3;
                    }
                }
            }
        }
    }

    // Epilogue: GRU update + spike + outputs
    const size_t N = (size_t)Tn * Bn * Cc * HWp;
    #pragma unroll
    for (int k = 0; k < 8; k++) {
        int oc = oc_base + ocq * 8 + k;
        float bias = b_f[oc];
        #pragma unroll
        for (int i = 0; i < 4; i++) {
            int gy  = ty0 + pyb + i;
            int gx  = tx0 + px;
            int pix = gy * Ww + gx;
            float xi = xt[((((size_t)t * Bn + b) * 192) + 128 + oc) * HWp + pix];
            float f  = acc[k][i] + bias + xi;
            float ig = tanhf(f);

            size_t sidx = (size_t)(b * Cc + oc) * HWp + pix;
            float u  = g_upd[sidx];
            float hp = (t > 0) ? g_h[sidx] : 0.0f;
            float h  = (1.0f - u) * hp + u * ig;

            float thr = g_thr[b * HWp + pix];
            float d   = h - thr;
            float ev  = (d > 0.0f) ? 1.0f : 0.0f;
            float y   = ev * h;
            float nd  = (d < 0.0f) ? (thr - h) : 0.0f;

            size_t o = (((size_t)t * Bn + b) * Cc + oc) * HWp + pix;
            out[o]         = y;
            out[N + o]     = ev;
            out[2 * N + o] = nd;

            g_prev_y[sidx] = y;
            g_h[sidx]      = h - ev * thr;
        }
    }
}

extern "C" void kernel_launch(void* const* d_in, const int* in_sizes, int n_in,
                              void* d_out, int out_size)
{
    const float* xt   = (const float*)d_in[0];
    const float* w_rz = (const float*)d_in[1];
    const float* b_rz = (const float*)d_in[2];
    const float* w_f  = (const float*)d_in[3];
    const float* b_f  = (const float*)d_in[4];
    // d_in[5] = stage (unused by reference)
    float* out = (float*)d_out;

    size_t smem = (size_t)SMEM_FLOATS * sizeof(float);  // 101,376 B
    cudaFuncSetAttribute(kA, cudaFuncAttributeMaxDynamicSharedMemorySize, (int)smem);
    cudaFuncSetAttribute(kB, cudaFuncAttributeMaxDynamicSharedMemorySize, (int)smem);

    dim3 gA(16, 5, Bn);
    dim3 gB(16, 2, Bn);
    for (int t = 0; t < Tn; t++) {
        kA<<<gA, 256, smem>>>(xt, w_rz, b_rz, t);
        kB<<<gB, 256, smem>>>(xt, w_f, b_f, out, t);
    }
}